// round 5
// baseline (speedup 1.0000x reference)
#include <cuda_runtime.h>
#include <math.h>

#define N_NAMED 8000
#define N_TOTAL 8192
#define DIM 128
#define BLOCKS 128
#define THREADS 256
#define WARPS 8
#define RPB (N_TOTAL / BLOCKS)   // 64 rows per block
#define RPW (RPB / WARPS)        // 8 rows per warp

// Cross-block scratch (no cudaMalloc allowed).
// g_pack[b] = (epoch << 32) | float_bits(block b's partial max)  — single 8B release store.
// g_epoch[b]: block-private replay counter (single writer & reader = block b).
__device__ unsigned long long g_pack[BLOCKS];
__device__ unsigned           g_epoch[BLOCKS];

__device__ __forceinline__ void st_rel64(unsigned long long* p, unsigned long long v) {
    asm volatile("st.release.gpu.global.u64 [%0], %1;" :: "l"(p), "l"(v) : "memory");
}
__device__ __forceinline__ unsigned long long ld_acq64(const unsigned long long* p) {
    unsigned long long v;
    asm volatile("ld.acquire.gpu.global.u64 %0, [%1];" : "=l"(v) : "l"(p) : "memory");
    return v;
}

__global__ void __launch_bounds__(THREADS)
falcon_fused(const float* __restrict__ anon,
             const float* __restrict__ etab,
             const float* __restrict__ ctab,
             const float* __restrict__ rtab,
             const float* __restrict__ w,    // [256]: w_l | w_r
             const float* __restrict__ bptr,
             const int*   __restrict__ cid,
             const int*   __restrict__ rid,
             float*       __restrict__ out)
{
    __shared__ float    s_w[2 * DIM];
    __shared__ float    s_dl[RPB];
    __shared__ float    s_max[WARPS];
    __shared__ float    s_part[4];     // per-poll-warp max partials
    __shared__ float    s_scal[3];     // c_dot, r_dot, b
    __shared__ unsigned s_epoch;

    const int tid  = threadIdx.x;
    const int warp = tid >> 5;
    const int lane = tid & 31;
    const int bid  = blockIdx.x;

    // epoch bump (block-private, plain ld/st; same value in every block each replay)
    if (tid == 0) {
        const unsigned e = g_epoch[bid] + 1u;
        g_epoch[bid] = e;
        s_epoch = e;
    }
    s_w[tid] = w[tid];
    __syncthreads();

    const float4 wl = reinterpret_cast<const float4*>(s_w)[lane];
    const float4 wr = reinterpret_cast<const float4*>(s_w + DIM)[lane];
    const unsigned e = s_epoch;

    // ---- batched row loads: 8 LDG.128 in flight per lane ----
    const int base = bid * RPB + warp * RPW;
    float4 v[RPW];
#pragma unroll
    for (int k = 0; k < RPW; ++k) {
        const int r = base + k;
        const float* ep = (r < N_NAMED)
                            ? (etab + (size_t)r * DIM)
                            : (anon + (size_t)(r - N_NAMED) * DIM);
        v[k] = reinterpret_cast<const float4*>(ep)[lane];
    }

    // ---- Phase A: w_r dots -> block max -> publish ONE 8B release store ----
    float lmax = -3.4e38f;
#pragma unroll
    for (int k = 0; k < RPW; ++k) {
        float dr = v[k].x * wr.x + v[k].y * wr.y + v[k].z * wr.z + v[k].w * wr.w;
#pragma unroll
        for (int o = 16; o > 0; o >>= 1)
            dr += __shfl_xor_sync(0xffffffffu, dr, o);
        lmax = fmaxf(lmax, dr);
    }
    if (lane == 0) s_max[warp] = lmax;
    __syncthreads();

    if (tid == 0) {
        float m = s_max[0];
#pragma unroll
        for (int i = 1; i < WARPS; ++i) m = fmaxf(m, s_max[i]);
        const unsigned long long pack =
            ((unsigned long long)e << 32) | (unsigned long long)__float_as_uint(m);
        st_rel64(&g_pack[bid], pack);          // no atomics, no contention
    }

    // ---- Phase B (overlaps other blocks' publishes): w_l dots ----
#pragma unroll
    for (int k = 0; k < RPW; ++k) {
        float dl = v[k].x * wl.x + v[k].y * wl.y + v[k].z * wl.z + v[k].w * wl.w;
#pragma unroll
        for (int o = 16; o > 0; o >>= 1)
            dl += __shfl_xor_sync(0xffffffffu, dl, o);
        if (lane == 0) s_dl[warp * RPW + k] = dl;
    }

    // ---- Phase C (also overlapped): scalar dots in warp 4 ----
    if (warp == 4) {
        const float* ce = ctab + (size_t)__ldg(cid) * DIM;
        const float* re = rtab + (size_t)__ldg(rid) * DIM;
        float cd = 0.f, rd = 0.f;
#pragma unroll
        for (int kk = 0; kk < 4; ++kk) {
            const float wlv = s_w[lane * 4 + kk];          // w_l
            cd += __ldg(&ce[lane * 4 + kk]) * wlv;
            rd += __ldg(&re[lane * 4 + kk]) * wlv;
        }
#pragma unroll
        for (int o = 16; o > 0; o >>= 1) {
            cd += __shfl_xor_sync(0xffffffffu, cd, o);
            rd += __shfl_xor_sync(0xffffffffu, rd, o);
        }
        if (lane == 0) {
            s_scal[0] = cd;
            s_scal[1] = rd;
            s_scal[2] = __ldg(bptr);
        }
    }

    // ---- Wait: 128 parallel pollers, one slot each; max rides in the same 8B ----
    if (tid < BLOCKS) {
        unsigned long long p = ld_acq64(&g_pack[tid]);
        while ((unsigned)(p >> 32) != e)
            p = ld_acq64(&g_pack[tid]);
        float m = __uint_as_float((unsigned)p);
#pragma unroll
        for (int o = 16; o > 0; o >>= 1)
            m = fmaxf(m, __shfl_xor_sync(0xffffffffu, m, o));
        if (lane == 0) s_part[warp] = m;
    }
    __syncthreads();

    // ---- outputs: exact collapse (both sigmoids strictly increase in col_j,
    //      so argmax_j sits at col_max for every i) ----
    if (tid < RPB) {
        const float cmax = fmaxf(fmaxf(s_part[0], s_part[1]),
                                 fmaxf(s_part[2], s_part[3]));
        const float b    = s_scal[2];
        const float cfs  = 1.f / (1.f + __expf(-(s_scal[0] + cmax + b)));
        const float rfs  = 1.f / (1.f + __expf(-(s_dl[tid] + s_scal[1] + cmax + b)));
        out[bid * RPB + tid] = rfs * cfs;
    }
}

extern "C" void kernel_launch(void* const* d_in, const int* in_sizes, int n_in,
                              void* d_out, int out_size) {
    const float* anon = (const float*)d_in[0];   // [192,128]
    const float* etab = (const float*)d_in[1];   // [8000,128]
    const float* ctab = (const float*)d_in[2];   // [100,128]
    const float* rtab = (const float*)d_in[3];   // [50,128]
    const float* w    = (const float*)d_in[4];   // [1,256]
    const float* bb   = (const float*)d_in[5];   // [1]
    const int*   cid  = (const int*)d_in[6];
    const int*   rid  = (const int*)d_in[7];

    falcon_fused<<<BLOCKS, THREADS>>>(anon, etab, ctab, rtab, w, bb, cid, rid,
                                      (float*)d_out);
}